// round 12
// baseline (speedup 1.0000x reference)
#include <cuda_runtime.h>
#include <cuda.h>
#include <math.h>
#include <stdint.h>

#define HH 64
#define WW 64
#define NUM_POS 48
#define CC 384
#define BB 32
#define ST 64             // tile row stride (floats); dense 64-wide rows

struct __align__(16) PosParam {
    float wx0, wx1, wx2;
    float wy0, wy1, wy2;
    int   ox, oy;
};

__device__ PosParam g_pp[NUM_POS];

// ---- tiny LUT kernel: separable normalized Gaussian weights per position ----
__global__ void precompute_weights(const float* __restrict__ offset)
{
    const int p = threadIdx.x;
    if (p >= NUM_POS) return;
    const float offx = offset[p * 2 + 0];
    const float offy = offset[p * 2 + 1];
    const float rx = rintf(offx);                 // == iw*16 exactly (jitter < 0.5)
    const float ry = rintf(offy);
    const float fx = offx - rx;
    const float fy = offy - ry;

    float gx[3], gy[3], sx = 0.f, sy = 0.f;
    #pragma unroll
    for (int k = 0; k < 3; k++) {
        const float dx = (float)(k - 1) + fx;
        const float dy = (float)(k - 1) + fy;
        gx[k] = expf(-2.0f * dx * dx);            // sigma = 0.5
        gy[k] = expf(-2.0f * dy * dy);
        sx += gx[k];
        sy += gy[k];
    }
    const float ix = 1.0f / sx, iy = 1.0f / sy;   // normalizer factors (separable)
    PosParam pp;
    pp.wx0 = gx[0] * ix; pp.wx1 = gx[1] * ix; pp.wx2 = gx[2] * ix;
    pp.wy0 = gy[0] * iy; pp.wy1 = gy[1] * iy; pp.wy2 = gy[2] * iy;
    pp.ox = (int)rx;     pp.oy = (int)ry;
    g_pp[p] = pp;
}

// ---- main fused kernel: TMA displaced load + separable-weight 3x3 conv ----
// TMA loads the 64x64 box at source coords (-ox, -oy): OOB elements zero-fill,
// which IS the reference's source-validity mask. tile row t holds displaced
// row t-1; rows 0 and 65 (conv zero padding) are zeroed by threads; the
// column padding (displaced cols -1/64) is handled by edge predicates.
//
// SMEM layout (one alignas(1024) array):
//   [0..31]          header: mbarrier at word 0-1; also underflow pad for
//                    speculative tile[-1] reads (value select-discarded)
//   [32..32+4223]    tile: 66 rows x 64 cols. TMA dst = tile+64 -> byte
//                    offset 384 = 3*128 (TMA needs 128B-aligned SMEM dst)
//   [.. +32]         tail pad for _r[4] overread at last row
__global__ __launch_bounds__(256, 8)
void displace_gauss_kernel(const __grid_constant__ CUtensorMap tmap,
                           float* __restrict__ out)
{
    __shared__ alignas(1024) float smem_all[32 + 66 * ST + 32];
    float* tile = smem_all + 32;

    const int c = blockIdx.x;
    const int b = blockIdx.y;
    const int tid = threadIdx.x;

    const PosParam pp = g_pp[c >> 3];

    uint32_t mbar_addr;
    {
        uint64_t t64;
        asm("cvta.to.shared.u64 %0, %1;" : "=l"(t64) : "l"(smem_all));
        mbar_addr = (uint32_t)t64;     // mbarrier lives at smem_all[0..1]
    }

    if (tid == 0) {
        asm volatile("mbarrier.init.shared.b64 [%0], %1;"
                     :: "r"(mbar_addr), "r"(1) : "memory");
    }
    __syncthreads();

    // zero conv-padding rows t=0 and t=65 (displaced y = -1 / 64)
    if (tid < 32) {
        const int t  = (tid < 16) ? 0 : 65;
        const int c4 = (tid & 15) << 2;
        *(float4*)&tile[t * ST + c4] = make_float4(0.f, 0.f, 0.f, 0.f);
    }

    // TMA: displaced 64x64 interior -> tile rows 1..64 (dst 128B-aligned)
    if (tid == 0) {
        const uint32_t dst_addr = mbar_addr + (32 + ST) * 4;
        asm volatile("mbarrier.arrive.expect_tx.shared.b64 _, [%0], %1;"
                     :: "r"(mbar_addr), "r"(HH * WW * 4) : "memory");
        const int plane = b * CC + c;
        asm volatile(
            "cp.async.bulk.tensor.3d.shared::cta.global.tile.mbarrier::complete_tx::bytes "
            "[%0], [%1, {%2, %3, %4}], [%5];"
            :: "r"(dst_addr), "l"(&tmap),
               "r"(-pp.ox), "r"(-pp.oy), "r"(plane),
               "r"(mbar_addr)
            : "memory");
    }

    // wait for TMA completion (phase 0)
    {
        uint32_t done;
        asm volatile(
            "{\n\t.reg .pred p;\n\t"
            "mbarrier.try_wait.parity.acquire.cta.shared::cta.b64 p, [%1], 0;\n\t"
            "selp.b32 %0, 1, 0, p;\n\t}"
            : "=r"(done) : "r"(mbar_addr) : "memory");
        if (!done) {
            asm volatile(
                "{\n\t.reg .pred P1;\n\t"
                "WL_%=:\n\t"
                "mbarrier.try_wait.parity.acquire.cta.shared::cta.b64 P1, [%0], 0, 0x989680;\n\t"
                "@P1 bra.uni WD_%=;\n\t"
                "bra.uni WL_%=;\n\t"
                "WD_%=:\n\t}"
                :: "r"(mbar_addr) : "memory");
        }
    }
    __syncthreads();   // also publishes the zeroed rows

    // --- 3x3 conv, separable weights, 4-col x 4-row patch per thread ---
    const int cg    = tid & 15;
    const int strip = tid >> 4;
    const int x4 = cg << 2;
    const int y0 = strip << 2;

    const float wx0 = pp.wx0, wx1 = pp.wx1, wx2 = pp.wx2;
    const float wy0 = pp.wy0, wy1 = pp.wy1, wy2 = pp.wy2;
    const bool has_lf = (cg != 0);
    const bool has_rt = (cg != 15);

    // hconv of tile row T (displaced row T-1): displaced cols -1/64 are zero
    #define HCONV(H, T)                                                        \
        {                                                                      \
            const float* _r = &tile[(T) * ST + x4];                            \
            const float  lf = has_lf ? _r[-1] : 0.f;                           \
            const float4 va = *(const float4*)_r;                              \
            const float  rt = has_rt ? _r[4] : 0.f;                            \
            H.x = fmaf(wx0, lf,   fmaf(wx1, va.x, wx2 * va.y));                \
            H.y = fmaf(wx0, va.x, fmaf(wx1, va.y, wx2 * va.z));                \
            H.z = fmaf(wx0, va.y, fmaf(wx1, va.z, wx2 * va.w));                \
            H.w = fmaf(wx0, va.z, fmaf(wx1, va.w, wx2 * rt));                  \
        }

    float* __restrict__ dst = out + ((size_t)b * CC + c) * (HH * WW);

    float4 h0, h1, hn;
    HCONV(h0, y0 + 0);                 // displaced row y0-1
    HCONV(h1, y0 + 1);                 // displaced row y0
    #pragma unroll
    for (int r = 0; r < 4; r++) {
        HCONV(hn, y0 + 2 + r);         // displaced row y0+r+1
        float4 o;
        o.x = fmaf(wy0, h0.x, fmaf(wy1, h1.x, wy2 * hn.x));
        o.y = fmaf(wy0, h0.y, fmaf(wy1, h1.y, wy2 * hn.y));
        o.z = fmaf(wy0, h0.z, fmaf(wy1, h1.z, wy2 * hn.z));
        o.w = fmaf(wy0, h0.w, fmaf(wy1, h1.w, wy2 * hn.w));
        *(float4*)&dst[(y0 + r) * WW + x4] = o;
        h0 = h1;
        h1 = hn;
    }
    #undef HCONV
}

// ---- host ----
typedef CUresult (*EncodeTiledFn)(
    CUtensorMap*, CUtensorMapDataType, cuuint32_t, void*,
    const cuuint64_t*, const cuuint64_t*, const cuuint32_t*, const cuuint32_t*,
    CUtensorMapInterleave, CUtensorMapSwizzle, CUtensorMapL2promotion,
    CUtensorMapFloatOOBfill);

extern "C" void kernel_launch(void* const* d_in, const int* in_sizes, int n_in,
                              void* d_out, int out_size)
{
    const float* inp    = (const float*)d_in[0];   // (32, 384, 64, 64) fp32
    const float* offset = (const float*)d_in[1];   // (48, 2) fp32
    float* out          = (float*)d_out;           // (32, 384, 64, 64) fp32

    // Build the TMA descriptor (host-only work; graph-capture safe).
    EncodeTiledFn encode = nullptr;
    cudaDriverEntryPointQueryResult qr;
    cudaGetDriverEntryPoint("cuTensorMapEncodeTiled", (void**)&encode,
                            cudaEnableDefault, &qr);

    CUtensorMap tmap;
    cuuint64_t dims[3]    = { WW, HH, (cuuint64_t)BB * CC };
    cuuint64_t strides[2] = { WW * sizeof(float), (cuuint64_t)HH * WW * sizeof(float) };
    cuuint32_t box[3]     = { WW, HH, 1 };
    cuuint32_t estr[3]    = { 1, 1, 1 };
    encode(&tmap, CU_TENSOR_MAP_DATA_TYPE_FLOAT32, 3, (void*)inp,
           dims, strides, box, estr,
           CU_TENSOR_MAP_INTERLEAVE_NONE, CU_TENSOR_MAP_SWIZZLE_NONE,
           CU_TENSOR_MAP_L2_PROMOTION_L2_128B,
           CU_TENSOR_MAP_FLOAT_OOB_FILL_NONE);

    precompute_weights<<<1, 64>>>(offset);
    dim3 grid(CC, BB);   // one CTA per (b, c) plane
    displace_gauss_kernel<<<grid, 256>>>(tmap, out);
}

// round 13
// speedup vs baseline: 1.6523x; 1.6523x over previous
#include <cuda_runtime.h>
#include <math.h>

#define HH 64
#define WW 64
#define NUM_POS 48
#define CC 384
#define BB 32

struct __align__(16) PosParam {
    float wx0, wx1, wx2;
    float wy0, wy1, wy2;
    int   ox, oy;
};

__device__ PosParam g_pp[NUM_POS];

// ---- tiny LUT kernel: separable normalized Gaussian weights per position ----
__global__ void precompute_weights(const float* __restrict__ offset)
{
    const int p = threadIdx.x;
    if (p >= NUM_POS) return;
    const float offx = offset[p * 2 + 0];
    const float offy = offset[p * 2 + 1];
    const float rx = rintf(offx);                 // == iw*16 exactly (jitter < 0.5)
    const float ry = rintf(offy);
    const float fx = offx - rx;
    const float fy = offy - ry;

    float gx[3], gy[3], sx = 0.f, sy = 0.f;
    #pragma unroll
    for (int k = 0; k < 3; k++) {
        const float dx = (float)(k - 1) + fx;
        const float dy = (float)(k - 1) + fy;
        gx[k] = expf(-2.0f * dx * dx);            // sigma = 0.5
        gy[k] = expf(-2.0f * dy * dy);
        sx += gx[k];
        sy += gy[k];
    }
    const float ix = 1.0f / sx, iy = 1.0f / sy;   // normalizer factors (separable)
    PosParam pp;
    pp.wx0 = gx[0] * ix; pp.wx1 = gx[1] * ix; pp.wx2 = gx[2] * ix;
    pp.wy0 = gy[0] * iy; pp.wy1 = gy[1] * iy; pp.wy2 = gy[2] * iy;
    pp.ox = (int)rx;     pp.oy = (int)ry;
    g_pp[p] = pp;
}

// ---- main fused kernel: displace + separable 3x3 Gaussian, NO smem ----
// Each thread: 4col x 4row patch, rolling hconv over 6 source rows read
// directly from global (L1/L2 serve halo overlap). All displacement and
// boundary masking folds into load predicates; ox,oy multiples of 16 keep
// every float4 window 4-aligned (no partial-vector validity cases).
__global__ __launch_bounds__(256, 6)
void displace_gauss_kernel(const float* __restrict__ inp,
                           float* __restrict__ out)
{
    const int c = blockIdx.x;
    const int b = blockIdx.y;
    const int tid = threadIdx.x;

    const PosParam pp = g_pp[c >> 3];
    const int ox = pp.ox, oy = pp.oy;   // multiples of 16 by construction
    const float wx0 = pp.wx0, wx1 = pp.wx1, wx2 = pp.wx2;
    const float wy0 = pp.wy0, wy1 = pp.wy1, wy2 = pp.wy2;

    const int cg    = tid & 15;         // column group: output cols x4..x4+3
    const int strip = tid >> 4;         // row strip:    output rows y0..y0+3
    const int x4 = cg << 2;
    const int y0 = strip << 2;

    const int sx = x4 - ox;             // source col of displaced col x4 (mult of 4)
    // main float4 (displaced cols x4..x4+3, always in displaced range):
    const bool okm = (unsigned)sx <= 60u;                      // sx in [0,60]
    // lf = D(row, x4-1): displaced ok iff cg>0; source col sx-1 in [0,64) iff sx in [4,64]
    const bool okl = (cg > 0)  && ((unsigned)(sx - 4) <= 60u);
    // rt = D(row, x4+4): displaced ok iff cg<15; source col sx+4 in [0,64) iff sx in [-4,56]
    const bool okr = (cg < 15) && ((unsigned)(sx + 4) <= 60u);

    const float* __restrict__ src = inp + ((size_t)b * CC + c) * (HH * WW);
    float* __restrict__ dst       = out + ((size_t)b * CC + c) * (HH * WW);

    float4 h0, h1, h2;
    #pragma unroll
    for (int k = 0; k < 6; k++) {
        const int y  = y0 - 1 + k;      // displaced row
        const int sy = y - oy;          // source row
        const bool rok = ((unsigned)y < (unsigned)HH) & ((unsigned)sy < (unsigned)HH);
        const float* r = src + sy * WW;

        float4 v = make_float4(0.f, 0.f, 0.f, 0.f);
        float lf = 0.f, rt = 0.f;
        if (rok & okm) v  = *(const float4*)(r + sx);
        if (rok & okl) lf = r[sx - 1];
        if (rok & okr) rt = r[sx + 4];

        // hconv: h[j] = wx0*D(col j-1) + wx1*D(col j) + wx2*D(col j+1)
        float4 h;
        h.x = fmaf(wx0, lf,  fmaf(wx1, v.x, wx2 * v.y));
        h.y = fmaf(wx0, v.x, fmaf(wx1, v.y, wx2 * v.z));
        h.z = fmaf(wx0, v.y, fmaf(wx1, v.z, wx2 * v.w));
        h.w = fmaf(wx0, v.z, fmaf(wx1, v.w, wx2 * rt));

        h0 = h1; h1 = h2; h2 = h;

        if (k >= 2) {
            // output row y-1 = y0+k-2 uses rows y-2,y-1,y -> h0,h1,h2
            float4 o;
            o.x = fmaf(wy0, h0.x, fmaf(wy1, h1.x, wy2 * h2.x));
            o.y = fmaf(wy0, h0.y, fmaf(wy1, h1.y, wy2 * h2.y));
            o.z = fmaf(wy0, h0.z, fmaf(wy1, h1.z, wy2 * h2.z));
            o.w = fmaf(wy0, h0.w, fmaf(wy1, h1.w, wy2 * h2.w));
            *(float4*)&dst[(y0 + k - 2) * WW + x4] = o;
        }
    }
}

extern "C" void kernel_launch(void* const* d_in, const int* in_sizes, int n_in,
                              void* d_out, int out_size)
{
    const float* inp    = (const float*)d_in[0];   // (32, 384, 64, 64) fp32
    const float* offset = (const float*)d_in[1];   // (48, 2) fp32
    float* out          = (float*)d_out;           // (32, 384, 64, 64) fp32

    precompute_weights<<<1, 64>>>(offset);
    dim3 grid(CC, BB);   // one CTA per (b, c) plane
    displace_gauss_kernel<<<grid, 256>>>(inp, out);
}